// round 9
// baseline (speedup 1.0000x reference)
#include <cuda_runtime.h>
#include <cuda_bf16.h>
#include <cstdint>

// Shapes (fixed by the problem)
static constexpr int Bc  = 2;
static constexpr int Sc  = 2048;
static constexpr int DMc = 512;
static constexpr int Hc  = 8;
static constexpr int DHc = 64;
static constexpr int BHc = Bc * Hc;          // 16
static constexpr int Mrows = Bc * Sc;        // 4096

// -------- device scratch (no allocations allowed) --------
__device__ float g_qp[Mrows * DMc];          // fp32 qp (for ab_kernel)
__device__ float g_outpre[Mrows * DMc];
__device__ float g_a[BHc * Sc];
__device__ float g_b[BHc * Sc];
__device__ float g_rmax[BHc * Sc];
__device__ float g_rinv[BHc * Sc];
// prepacked bf16 hi/lo: Q,K row-major packed 2-per-u32; V transposed per head
__device__ __align__(16) uint32_t g_qph[Mrows * DMc / 2];
__device__ __align__(16) uint32_t g_qpl[Mrows * DMc / 2];
__device__ __align__(16) uint32_t g_kph[Mrows * DMc / 2];
__device__ __align__(16) uint32_t g_kpl[Mrows * DMc / 2];
__device__ __align__(16) __nv_bfloat16 g_vth[Mrows * DMc];   // [bh][d][s]
__device__ __align__(16) __nv_bfloat16 g_vtl[Mrows * DMc];

// ==================== warp-mma helpers ====================
__device__ __forceinline__ uint32_t smem_u32(const void* p) {
    uint32_t a;
    asm("{ .reg .u64 t; cvta.to.shared.u64 t, %1; cvt.u32.u64 %0, t; }" : "=r"(a) : "l"(p));
    return a;
}
__device__ __forceinline__ void ldsm4(uint32_t (&r)[4], uint32_t addr) {
    asm volatile("ldmatrix.sync.aligned.m8n8.x4.shared.b16 {%0,%1,%2,%3}, [%4];"
        : "=r"(r[0]), "=r"(r[1]), "=r"(r[2]), "=r"(r[3]) : "r"(addr));
}
__device__ __forceinline__ void mma16816(float (&c)[4], const uint32_t (&a)[4],
                                         uint32_t b0, uint32_t b1) {
    asm volatile(
        "mma.sync.aligned.m16n8k16.row.col.f32.bf16.bf16.f32 "
        "{%0,%1,%2,%3}, {%4,%5,%6,%7}, {%8,%9}, {%0,%1,%2,%3};"
        : "+f"(c[0]), "+f"(c[1]), "+f"(c[2]), "+f"(c[3])
        : "r"(a[0]), "r"(a[1]), "r"(a[2]), "r"(a[3]), "r"(b0), "r"(b1));
}
__device__ __forceinline__ uint32_t addrA(uint32_t base, int r0, int k0, int lane, int stride) {
    return base + (uint32_t)(((r0 + (lane & 15)) * stride + (k0 >> 1) + (lane >> 4) * 4) * 4);
}
__device__ __forceinline__ uint32_t addrB(uint32_t base, int n0, int k0, int lane, int stride) {
    int r = n0 + (lane & 7) + ((lane >> 4) & 1) * 8;
    int c = (k0 >> 1) + ((lane >> 3) & 1) * 4;
    return base + (uint32_t)((r * stride + c) * 4);
}
__device__ __forceinline__ void split2(float x0, float x1, uint32_t& hi, uint32_t& lo) {
    __nv_bfloat16 h0 = __float2bfloat16(x0), h1 = __float2bfloat16(x1);
    float r0 = x0 - __bfloat162float(h0), r1 = x1 - __bfloat162float(h1);
    __nv_bfloat16 l0 = __float2bfloat16(r0), l1 = __float2bfloat16(r1);
    hi = (uint32_t)__bfloat16_as_ushort(h0) | ((uint32_t)__bfloat16_as_ushort(h1) << 16);
    lo = (uint32_t)__bfloat16_as_ushort(l0) | ((uint32_t)__bfloat16_as_ushort(l1) << 16);
}

// ============================================================
// GEMM body: C[M,512] = A[M,512] @ W[512,512] + bias  (split precision)
// block 256 (8 warps: 4 m x 2 n), tile 128x128, warp tile 32x64
// ============================================================
__device__ __forceinline__ void gemm_body(
    const float* __restrict__ A, const float* __restrict__ W,
    const float* __restrict__ bias,
    float* __restrict__ C, uint32_t* __restrict__ Hp, uint32_t* __restrict__ Lp,
    __nv_bfloat16* __restrict__ Ht, __nv_bfloat16* __restrict__ Lt,
    bool writeF, bool writeP, bool writeT, int mb, int nb)
{
    __shared__ uint32_t sm[4 * 128 * 20];
    const int ASH = 0, ASL = 2560, BSH = 5120, BSL = 7680, RS = 20;

    const int tid = threadIdx.x;
    const int w = tid >> 5, lane = tid & 31;
    const int g = lane >> 2, t = lane & 3;
    const int wm = (w >> 1) * 32, wn = (w & 1) * 64;
    const uint32_t sbase = smem_u32(sm);

    float c[2][8][4];
#pragma unroll
    for (int mi = 0; mi < 2; mi++)
#pragma unroll
        for (int nf = 0; nf < 8; nf++)
#pragma unroll
            for (int r = 0; r < 4; r++) c[mi][nf][r] = 0.f;

    const int arow_i = tid >> 1, aseg = tid & 1;
    const float* arow = A + (size_t)(mb + arow_i) * DMc;
    const int bn = tid & 127, bkh = tid >> 7;

    for (int kc = 0; kc < 16; kc++) {
#pragma unroll
        for (int i = 0; i < 4; i++) {
            int f4 = aseg * 4 + i;
            float4 v = *(const float4*)(arow + kc * 32 + f4 * 4);
            uint32_t h0, l0, h1, l1;
            split2(v.x, v.y, h0, l0);
            split2(v.z, v.w, h1, l1);
            sm[ASH + arow_i * RS + f4 * 2]     = h0;
            sm[ASH + arow_i * RS + f4 * 2 + 1] = h1;
            sm[ASL + arow_i * RS + f4 * 2]     = l0;
            sm[ASL + arow_i * RS + f4 * 2 + 1] = l1;
        }
#pragma unroll
        for (int i = 0; i < 8; i++) {
            int kp = bkh * 8 + i;
            const float* wp = W + (size_t)(kc * 32 + 2 * kp) * DMc + nb + bn;
            float w0 = wp[0], w1 = wp[DMc];
            uint32_t hi, lo;
            split2(w0, w1, hi, lo);
            sm[BSH + bn * RS + kp] = hi;
            sm[BSL + bn * RS + kp] = lo;
        }
        __syncthreads();

#pragma unroll
        for (int kk = 0; kk < 2; kk++) {
            uint32_t ah[2][4], al[2][4];
#pragma unroll
            for (int mi = 0; mi < 2; mi++) {
                ldsm4(ah[mi], addrA(sbase + ASH * 4, wm + mi * 16, kk * 16, lane, RS));
                ldsm4(al[mi], addrA(sbase + ASL * 4, wm + mi * 16, kk * 16, lane, RS));
            }
#pragma unroll
            for (int nb2 = 0; nb2 < 4; nb2++) {
                uint32_t bhf[4], blf[4];
                ldsm4(bhf, addrB(sbase + BSH * 4, wn + nb2 * 16, kk * 16, lane, RS));
                ldsm4(blf, addrB(sbase + BSL * 4, wn + nb2 * 16, kk * 16, lane, RS));
#pragma unroll
                for (int mi = 0; mi < 2; mi++) {
                    mma16816(c[mi][2 * nb2],     ah[mi], bhf[0], bhf[1]);
                    mma16816(c[mi][2 * nb2],     ah[mi], blf[0], blf[1]);
                    mma16816(c[mi][2 * nb2],     al[mi], bhf[0], bhf[1]);
                    mma16816(c[mi][2 * nb2 + 1], ah[mi], bhf[2], bhf[3]);
                    mma16816(c[mi][2 * nb2 + 1], ah[mi], blf[2], blf[3]);
                    mma16816(c[mi][2 * nb2 + 1], al[mi], bhf[2], bhf[3]);
                }
            }
        }
        __syncthreads();
    }

#pragma unroll
    for (int mi = 0; mi < 2; mi++)
#pragma unroll
        for (int hh = 0; hh < 2; hh++) {
            int row = mb + wm + mi * 16 + hh * 8 + g;
#pragma unroll
            for (int nf = 0; nf < 8; nf++) {
                int col = nb + wn + nf * 8 + 2 * t;
                float2 bv = *(const float2*)(bias + col);
                float ox = c[mi][nf][hh * 2 + 0] + bv.x;
                float oy = c[mi][nf][hh * 2 + 1] + bv.y;
                if (writeF)
                    *(float2*)(C + (size_t)row * DMc + col) = make_float2(ox, oy);
                if (writeP) {
                    uint32_t hi, lo;
                    split2(ox, oy, hi, lo);
                    size_t pi = ((size_t)row * DMc + col) >> 1;
                    Hp[pi] = hi;
                    Lp[pi] = lo;
                }
                if (writeT) {
                    __nv_bfloat16 h0 = __float2bfloat16(ox);
                    __nv_bfloat16 l0 = __float2bfloat16(ox - __bfloat162float(h0));
                    __nv_bfloat16 h1 = __float2bfloat16(oy);
                    __nv_bfloat16 l1 = __float2bfloat16(oy - __bfloat162float(h1));
                    size_t i0 = ((size_t)(((row >> 11) * Hc + (col >> 6)) * DHc + (col & 63))) * Sc
                              + (row & (Sc - 1));
                    Ht[i0] = h0; Lt[i0] = l0;
                    Ht[i0 + Sc] = h1; Lt[i0 + Sc] = l1;
                }
            }
        }
}

// K1: fused Q/K/V projections. grid = (4, 32, 3), block 256.
__global__ __launch_bounds__(256, 1)
void qkv_kernel(const float* __restrict__ q, const float* __restrict__ k,
                const float* __restrict__ v,
                const float* __restrict__ Wq, const float* __restrict__ Wk,
                const float* __restrict__ Wv,
                const float* __restrict__ bq, const float* __restrict__ bk,
                const float* __restrict__ bv)
{
    const int mb = blockIdx.y * 128, nb = blockIdx.x * 128;
    if (blockIdx.z == 0)
        gemm_body(q, Wq, bq, g_qp, g_qph, g_qpl, nullptr, nullptr, true, true, false, mb, nb);
    else if (blockIdx.z == 1)
        gemm_body(k, Wk, bk, nullptr, g_kph, g_kpl, nullptr, nullptr, false, true, false, mb, nb);
    else
        gemm_body(v, Wv, bv, nullptr, nullptr, nullptr, g_vth, g_vtl, false, false, true, mb, nb);
}

// K5: final projection. grid = (4, 32), block 256.
__global__ __launch_bounds__(256, 1)
void out_kernel(const float* __restrict__ Wo, const float* __restrict__ bo,
                float* __restrict__ out)
{
    gemm_body(g_outpre, Wo, bo, out, nullptr, nullptr, nullptr, nullptr,
              true, false, false, blockIdx.y * 128, blockIdx.x * 128);
}

// ============================================================
// K2: a,b heads. grid = 128, block 256, warp handles 4 rows, W cached in smem.
// ============================================================
__global__ __launch_bounds__(256)
void ab_kernel(const float* __restrict__ Wa, const float* __restrict__ ba,
               const float* __restrict__ Wb, const float* __restrict__ bb)
{
    __shared__ float4 sWa[512][2];
    __shared__ float4 sWb[512][2];
    const int tid = threadIdx.x;
#pragma unroll
    for (int i = 0; i < 4; i++) {
        int idx = tid + i * 256;
        ((float4*)sWa)[idx] = ((const float4*)Wa)[idx];
        ((float4*)sWb)[idx] = ((const float4*)Wb)[idx];
    }
    __syncthreads();

    const int w = tid >> 5, lane = tid & 31;
    const int rbase = blockIdx.x * 32 + w * 4;

    float acc[4][16];
#pragma unroll
    for (int j = 0; j < 4; j++)
#pragma unroll
        for (int h = 0; h < 16; h++) acc[j][h] = 0.f;

#pragma unroll
    for (int tt = 0; tt < 4; tt++) {
        const int d0 = tt * 128 + lane * 4;
        float4 x[4];
#pragma unroll
        for (int j = 0; j < 4; j++)
            x[j] = *(const float4*)(g_qp + (size_t)(rbase + j) * DMc + d0);
#pragma unroll
        for (int dd = 0; dd < 4; dd++) {
            float4 wa0 = sWa[d0 + dd][0], wa1 = sWa[d0 + dd][1];
            float4 wb0 = sWb[d0 + dd][0], wb1 = sWb[d0 + dd][1];
#pragma unroll
            for (int j = 0; j < 4; j++) {
                float xv = (&x[j].x)[dd];
                acc[j][0]  = fmaf(xv, wa0.x, acc[j][0]);
                acc[j][1]  = fmaf(xv, wa0.y, acc[j][1]);
                acc[j][2]  = fmaf(xv, wa0.z, acc[j][2]);
                acc[j][3]  = fmaf(xv, wa0.w, acc[j][3]);
                acc[j][4]  = fmaf(xv, wa1.x, acc[j][4]);
                acc[j][5]  = fmaf(xv, wa1.y, acc[j][5]);
                acc[j][6]  = fmaf(xv, wa1.z, acc[j][6]);
                acc[j][7]  = fmaf(xv, wa1.w, acc[j][7]);
                acc[j][8]  = fmaf(xv, wb0.x, acc[j][8]);
                acc[j][9]  = fmaf(xv, wb0.y, acc[j][9]);
                acc[j][10] = fmaf(xv, wb0.z, acc[j][10]);
                acc[j][11] = fmaf(xv, wb0.w, acc[j][11]);
                acc[j][12] = fmaf(xv, wb1.x, acc[j][12]);
                acc[j][13] = fmaf(xv, wb1.y, acc[j][13]);
                acc[j][14] = fmaf(xv, wb1.z, acc[j][14]);
                acc[j][15] = fmaf(xv, wb1.w, acc[j][15]);
            }
        }
    }
#pragma unroll
    for (int o = 16; o > 0; o >>= 1)
#pragma unroll
        for (int j = 0; j < 4; j++)
#pragma unroll
            for (int h = 0; h < 16; h++)
                acc[j][h] += __shfl_xor_sync(0xffffffff, acc[j][h], o);

    if (lane < 4) {
        int row = rbase + lane;
        int b = row >> 11, s = row & (Sc - 1);
#pragma unroll
        for (int h = 0; h < 8; h++) {
            g_a[(b * Hc + h) * Sc + s] = acc[lane][h] + ba[h];
            g_b[(b * Hc + h) * Sc + s] = acc[lane][h + 8] + bb[h];
        }
    }
}

// Shared smem layout for stats kernel (dynamic, 73728 B)
static constexpr int QH_O = 0, QL_O = 4608, KVH_O = 9216, KVL_O = 13824;
static constexpr int RSQ = 36;
static constexpr int DYN_SMEM = 18432 * 4;

// copy 128 rows x 64 bf16 (32 u32) from packed global hi/lo into smem stride-36 rows
__device__ __forceinline__ void stage_copy(uint32_t* sm, int offH, int offL,
        const uint32_t* __restrict__ srcH, const uint32_t* __restrict__ srcL,
        size_t rowbase, int tid)
{
    const int row = tid >> 1, half = tid & 1;
    const size_t s0 = rowbase + (size_t)row * (DMc / 2) + half * 16;
    const uint4* sH = (const uint4*)(srcH + s0);
    const uint4* sL = (const uint4*)(srcL + s0);
    uint4* dH = (uint4*)(sm + offH + row * RSQ + half * 16);
    uint4* dL = (uint4*)(sm + offL + row * RSQ + half * 16);
#pragma unroll
    for (int i = 0; i < 4; i++) { dH[i] = sH[i]; dL[i] = sL[i]; }
}

__device__ __forceinline__ void score_mma(float (&c)[2][8][4], uint32_t sbase,
                                          int wm, int wn, int lane)
{
#pragma unroll
    for (int mi = 0; mi < 2; mi++)
#pragma unroll
        for (int nf = 0; nf < 8; nf++)
#pragma unroll
            for (int r = 0; r < 4; r++) c[mi][nf][r] = 0.f;
#pragma unroll
    for (int kk = 0; kk < 4; kk++) {
        uint32_t ah[2][4], al[2][4];
#pragma unroll
        for (int mi = 0; mi < 2; mi++) {
            ldsm4(ah[mi], addrA(sbase + QH_O * 4, wm + mi * 16, kk * 16, lane, RSQ));
            ldsm4(al[mi], addrA(sbase + QL_O * 4, wm + mi * 16, kk * 16, lane, RSQ));
        }
#pragma unroll
        for (int nb2 = 0; nb2 < 4; nb2++) {
            uint32_t bhf[4], blf[4];
            ldsm4(bhf, addrB(sbase + KVH_O * 4, wn + nb2 * 16, kk * 16, lane, RSQ));
            ldsm4(blf, addrB(sbase + KVL_O * 4, wn + nb2 * 16, kk * 16, lane, RSQ));
#pragma unroll
            for (int mi = 0; mi < 2; mi++) {
                mma16816(c[mi][2 * nb2],     ah[mi], bhf[0], bhf[1]);
                mma16816(c[mi][2 * nb2],     ah[mi], blf[0], blf[1]);
                mma16816(c[mi][2 * nb2],     al[mi], bhf[0], bhf[1]);
                mma16816(c[mi][2 * nb2 + 1], ah[mi], bhf[2], bhf[3]);
                mma16816(c[mi][2 * nb2 + 1], ah[mi], blf[2], blf[3]);
                mma16816(c[mi][2 * nb2 + 1], al[mi], bhf[2], bhf[3]);
            }
        }
    }
}

// ============================================================
// K3: stats — scores + full logit epilogue, WRITES raw logits, online max/sum.
// grid = (16 qtile, 16 bh), block = 256.
// ============================================================
__global__ __launch_bounds__(256, 1)
void stats_tc_kernel(const float* __restrict__ xdiff, const int* __restrict__ mask,
                     float* __restrict__ attn)
{
    extern __shared__ uint32_t sm[];
    const int tid = threadIdx.x, w = tid >> 5, lane = tid & 31;
    const int g = lane >> 2, t = lane & 3;
    const int bh = blockIdx.y, b = bh >> 3, h = bh & 7;
    const int qb = blockIdx.x * 128;
    const int wm = (w >> 1) * 32, wn = (w & 1) * 64;
    const uint32_t sbase = smem_u32(sm);

    stage_copy(sm, QH_O, QL_O, g_qph, g_qpl,
               (size_t)(b * Sc + qb) * (DMc / 2) + h * (DHc / 2), tid);
    __syncthreads();

    float rm[4], rs[4], aqv[4], bqv[4];
    const float* xr[4];
    float* lrow[4];
#pragma unroll
    for (int mi = 0; mi < 2; mi++)
#pragma unroll
        for (int hh = 0; hh < 2; hh++) {
            int idx = mi * 2 + hh;
            int q = qb + wm + mi * 16 + hh * 8 + g;
            rm[idx] = -3.0e38f; rs[idx] = 0.f;
            aqv[idx] = g_a[bh * Sc + q];
            bqv[idx] = g_b[bh * Sc + q];
            xr[idx] = xdiff + ((size_t)b * Sc + q) * Sc;
            lrow[idx] = attn + ((size_t)bh * Sc + q) * Sc;
        }
    const int* mrow = mask + b * Sc;

    for (int kt = 0; kt < 16; kt++) {
        const int kb = kt * 128;
        stage_copy(sm, KVH_O, KVL_O, g_kph, g_kpl,
                   (size_t)(b * Sc + kb) * (DMc / 2) + h * (DHc / 2), tid);
        __syncthreads();

        float c[2][8][4];
        score_mma(c, sbase, wm, wn, lane);
        __syncthreads();

#pragma unroll
        for (int mi = 0; mi < 2; mi++)
#pragma unroll
            for (int nf = 0; nf < 8; nf++) {
                int col = kb + wn + nf * 8 + 2 * t;
                int2 mv = *(const int2*)(mrow + col);
                float mt0 = (float)mv.x * -1e9f, mt1 = (float)mv.y * -1e9f;
#pragma unroll
                for (int hh = 0; hh < 2; hh++) {
                    int idx = mi * 2 + hh;
                    float2 xd = *(const float2*)(xr[idx] + col);
                    float l0 = c[mi][nf][hh * 2 + 0] * 0.125f + mt0 + aqv[idx] * xd.x + bqv[idx] * xd.x * xd.x;
                    float l1 = c[mi][nf][hh * 2 + 1] * 0.125f + mt1 + aqv[idx] * xd.y + bqv[idx] * xd.y * xd.y;
                    *(float2*)(lrow[idx] + col) = make_float2(l0, l1);
                    float mx = fmaxf(l0, l1);
                    if (mx > rm[idx]) { rs[idx] *= __expf(rm[idx] - mx); rm[idx] = mx; }
                    rs[idx] += __expf(l0 - rm[idx]) + __expf(l1 - rm[idx]);
                }
            }
    }

    // quad reduce
#pragma unroll
    for (int off = 1; off <= 2; off <<= 1)
#pragma unroll
        for (int i = 0; i < 4; i++) {
            float om = __shfl_xor_sync(0xffffffff, rm[i], off);
            float os = __shfl_xor_sync(0xffffffff, rs[i], off);
            float nm = fmaxf(rm[i], om);
            rs[i] = rs[i] * __expf(rm[i] - nm) + os * __expf(om - nm);
            rm[i] = nm;
        }
    __syncthreads();
    float2* red = (float2*)sm;
    if (t == 0) {
#pragma unroll
        for (int i = 0; i < 4; i++) {
            int rl = (i >> 1) * 16 + (i & 1) * 8 + g;
            red[w * 32 + rl] = make_float2(rm[i], rs[i]);
        }
    }
    __syncthreads();
    if (!(w & 1) && t == 0) {
#pragma unroll
        for (int i = 0; i < 4; i++) {
            int rl = (i >> 1) * 16 + (i & 1) * 8 + g;
            float2 p = red[(w ^ 1) * 32 + rl];
            float nm = fmaxf(rm[i], p.x);
            float ns = rs[i] * __expf(rm[i] - nm) + p.y * __expf(p.x - nm);
            int q = qb + wm + rl;
            g_rmax[bh * Sc + q] = nm;
            g_rinv[bh * Sc + q] = 1.0f / ns;
        }
    }
}

// ============================================================
// K4: attnV — fully-coalesced redesign.
// grid = (16 qtile128, 16 bh), block = 256 (8 warps, each owns 16 q rows).
// Per 64-k chunk: coalesced logit float4 load -> exp -> coalesced attn write
// -> P(bf16 hi/lo) to smem -> warp MMA (k-serial, no output reduce).
// smem: PH[128][36], PL[128][36], VH[64][36], VL[64][36] = 55296 B (dynamic).
// ============================================================
static constexpr int PH_O = 0, PL_O = 4608, VH_O = 9216, VL_O = 11520;
static constexpr int AV_SMEM = 13824 * 4;   // 55296 B

__global__ __launch_bounds__(256)
void attnv_tc_kernel(float* __restrict__ attn)
{
    extern __shared__ uint32_t sm[];
    const int tid = threadIdx.x, w = tid >> 5, lane = tid & 31;
    const int g = lane >> 2, t = lane & 3;
    const int bh = blockIdx.y;
    const int qb = blockIdx.x * 128;
    const int wm = w * 16;                      // warp owns q rows wm..wm+15
    const uint32_t sbase = smem_u32(sm);

    // phase-1 row assignment (fixed across chunks)
    const int prow = tid >> 1, pseg = tid & 1;  // 2 threads per q row, 32 cols each
    const int pq = qb + prow;
    const float pms  = g_rmax[bh * Sc + pq];
    const float pinv = g_rinv[bh * Sc + pq];
    float* parow = attn + ((size_t)bh * Sc + pq) * Sc;

    // V staging assignment
    const int vrow = tid >> 2, vseg = tid & 3;  // 64 d rows, 4 threads/row (2 uint4 each)

    float o[8][4];
#pragma unroll
    for (int nf = 0; nf < 8; nf++)
#pragma unroll
        for (int r = 0; r < 4; r++) o[nf][r] = 0.f;

    for (int kt = 0; kt < 32; kt++) {
        const int kb = kt * 64;

        // ---- phase 1: coalesced softmax + P into smem ----
        {
            float4 Lv[8];
            const float* src = parow + kb + pseg * 32;
#pragma unroll
            for (int i = 0; i < 8; i++) Lv[i] = *(const float4*)(src + i * 4);
#pragma unroll
            for (int i = 0; i < 8; i++) {
                float4 p;
                p.x = __expf(Lv[i].x - pms) * pinv;
                p.y = __expf(Lv[i].y - pms) * pinv;
                p.z = __expf(Lv[i].z - pms) * pinv;
                p.w = __expf(Lv[i].w - pms) * pinv;
                *(float4*)(parow + kb + pseg * 32 + i * 4) = p;
                uint32_t h0, l0, h1, l1;
                split2(p.x, p.y, h0, l0);
                split2(p.z, p.w, h1, l1);
                int base = prow * RSQ + pseg * 16 + i * 2;
                sm[PH_O + base]     = h0;
                sm[PH_O + base + 1] = h1;
                sm[PL_O + base]     = l0;
                sm[PL_O + base + 1] = l1;
            }
        }
        // ---- phase 2: stage V^T chunk (64 d x 64 k) ----
        {
            const uint4* sH = (const uint4*)g_vth + ((size_t)(bh * DHc + vrow) * Sc + kb) / 8;
            const uint4* sL = (const uint4*)g_vtl + ((size_t)(bh * DHc + vrow) * Sc + kb) / 8;
            uint4* dH = (uint4*)(sm + VH_O + vrow * RSQ) + vseg * 2;
            uint4* dL = (uint4*)(sm + VL_O + vrow * RSQ) + vseg * 2;
            dH[0] = sH[vseg * 2];
            dH[1] = sH[vseg * 2 + 1];
            dL[0] = sL[vseg * 2];
            dL[1] = sL[vseg * 2 + 1];
        }
        __syncthreads();

        // ---- phase 3: MMA — warp tile 16q x 64d, K = 64 chunk ----
#pragma unroll
        for (int kk = 0; kk < 4; kk++) {
            uint32_t ph[4], pl[4];
            ldsm4(ph, addrA(sbase + PH_O * 4, wm, kk * 16, lane, RSQ));
            ldsm4(pl, addrA(sbase + PL_O * 4, wm, kk * 16, lane, RSQ));
#pragma unroll
            for (int nd = 0; nd < 4; nd++) {
                uint32_t vh[4], vl[4];
                ldsm4(vh, addrB(sbase + VH_O * 4, nd * 16, kk * 16, lane, RSQ));
                ldsm4(vl, addrB(sbase + VL_O * 4, nd * 16, kk * 16, lane, RSQ));
                mma16816(o[2 * nd],     ph, vh[0], vh[1]);
                mma16816(o[2 * nd],     ph, vl[0], vl[1]);
                mma16816(o[2 * nd],     pl, vh[0], vh[1]);
                mma16816(o[2 * nd + 1], ph, vh[2], vh[3]);
                mma16816(o[2 * nd + 1], ph, vl[2], vl[3]);
                mma16816(o[2 * nd + 1], pl, vh[2], vh[3]);
            }
        }
        __syncthreads();
    }

    // output: warp-private rows, no reduce needed
    const int b = bh >> 3, h = bh & 7;
#pragma unroll
    for (int hh = 0; hh < 2; hh++) {
        int q = qb + wm + hh * 8 + g;
#pragma unroll
        for (int nf = 0; nf < 8; nf++) {
            float2 val = make_float2(o[nf][hh * 2 + 0], o[nf][hh * 2 + 1]);
            *(float2*)(g_outpre + (size_t)(b * Sc + q) * DMc + h * DHc + nf * 8 + 2 * t) = val;
        }
    }
}

// ============================================================
extern "C" void kernel_launch(void* const* d_in, const int* in_sizes, int n_in,
                              void* d_out, int out_size)
{
    const float* q     = (const float*)d_in[0];
    const float* k     = (const float*)d_in[1];
    const float* v     = (const float*)d_in[2];
    const float* xdiff = (const float*)d_in[3];
    const int*   mask  = (const int*)d_in[4];
    const float* Wq = (const float*)d_in[5];
    const float* bq = (const float*)d_in[6];
    const float* Wk = (const float*)d_in[7];
    const float* bk = (const float*)d_in[8];
    const float* Wv = (const float*)d_in[9];
    const float* bv = (const float*)d_in[10];
    const float* Wa = (const float*)d_in[11];
    const float* ba = (const float*)d_in[12];
    const float* Wb = (const float*)d_in[13];
    const float* bb = (const float*)d_in[14];
    const float* Wo = (const float*)d_in[15];
    const float* bo = (const float*)d_in[16];

    float* out  = (float*)d_out;                 // (B,S,DM)
    float* attn = out + (size_t)Bc * Sc * DMc;   // (B,H,S,S)

    cudaFuncSetAttribute(stats_tc_kernel, cudaFuncAttributeMaxDynamicSharedMemorySize, DYN_SMEM);
    cudaFuncSetAttribute(attnv_tc_kernel, cudaFuncAttributeMaxDynamicSharedMemorySize, AV_SMEM);

    qkv_kernel<<<dim3(DMc / 128, Mrows / 128, 3), 256>>>(q, k, v, Wq, Wk, Wv, bq, bk, bv);
    ab_kernel<<<Mrows / 32, 256>>>(Wa, ba, Wb, bb);
    stats_tc_kernel<<<dim3(Sc / 128, BHc), 256, DYN_SMEM>>>(xdiff, mask, attn);
    attnv_tc_kernel<<<dim3(Sc / 128, BHc), 256, AV_SMEM>>>(attn);
    out_kernel<<<dim3(DMc / 128, Mrows / 128), 256>>>(Wo, bo, out);
}

// round 10
// speedup vs baseline: 1.8282x; 1.8282x over previous
#include <cuda_runtime.h>
#include <cuda_bf16.h>
#include <cstdint>

// Shapes (fixed by the problem)
static constexpr int Bc  = 2;
static constexpr int Sc  = 2048;
static constexpr int DMc = 512;
static constexpr int Hc  = 8;
static constexpr int DHc = 64;
static constexpr int BHc = Bc * Hc;          // 16
static constexpr int Mrows = Bc * Sc;        // 4096
static constexpr int KS   = 4;               // key-dimension splits

// -------- device scratch (no allocations allowed) --------
__device__ float g_qp[Mrows * DMc];          // fp32 qp (for ab_kernel)
__device__ float g_opart[KS * Mrows * DMc];  // partial attn@V outputs (32 MB)
__device__ float g_a[BHc * Sc];
__device__ float g_b[BHc * Sc];
__device__ float g_rmax[BHc * Sc];
__device__ float g_rinv[BHc * Sc];
__device__ float2 g_pstat[KS * BHc * Sc];    // partial (max, sum)
// prepacked bf16 hi/lo: Q,K row-major packed 2-per-u32; V transposed per head
__device__ __align__(16) uint32_t g_qph[Mrows * DMc / 2];
__device__ __align__(16) uint32_t g_qpl[Mrows * DMc / 2];
__device__ __align__(16) uint32_t g_kph[Mrows * DMc / 2];
__device__ __align__(16) uint32_t g_kpl[Mrows * DMc / 2];
__device__ __align__(16) __nv_bfloat16 g_vth[Mrows * DMc];   // [bh][d][s]
__device__ __align__(16) __nv_bfloat16 g_vtl[Mrows * DMc];

// ==================== warp-mma helpers ====================
__device__ __forceinline__ uint32_t smem_u32(const void* p) {
    uint32_t a;
    asm("{ .reg .u64 t; cvta.to.shared.u64 t, %1; cvt.u32.u64 %0, t; }" : "=r"(a) : "l"(p));
    return a;
}
__device__ __forceinline__ void ldsm4(uint32_t (&r)[4], uint32_t addr) {
    asm volatile("ldmatrix.sync.aligned.m8n8.x4.shared.b16 {%0,%1,%2,%3}, [%4];"
        : "=r"(r[0]), "=r"(r[1]), "=r"(r[2]), "=r"(r[3]) : "r"(addr));
}
__device__ __forceinline__ void mma16816(float (&c)[4], const uint32_t (&a)[4],
                                         uint32_t b0, uint32_t b1) {
    asm volatile(
        "mma.sync.aligned.m16n8k16.row.col.f32.bf16.bf16.f32 "
        "{%0,%1,%2,%3}, {%4,%5,%6,%7}, {%8,%9}, {%0,%1,%2,%3};"
        : "+f"(c[0]), "+f"(c[1]), "+f"(c[2]), "+f"(c[3])
        : "r"(a[0]), "r"(a[1]), "r"(a[2]), "r"(a[3]), "r"(b0), "r"(b1));
}
__device__ __forceinline__ uint32_t addrA(uint32_t base, int r0, int k0, int lane, int stride) {
    return base + (uint32_t)(((r0 + (lane & 15)) * stride + (k0 >> 1) + (lane >> 4) * 4) * 4);
}
__device__ __forceinline__ uint32_t addrB(uint32_t base, int n0, int k0, int lane, int stride) {
    int r = n0 + (lane & 7) + ((lane >> 4) & 1) * 8;
    int c = (k0 >> 1) + ((lane >> 3) & 1) * 4;
    return base + (uint32_t)((r * stride + c) * 4);
}
__device__ __forceinline__ void split2(float x0, float x1, uint32_t& hi, uint32_t& lo) {
    __nv_bfloat16 h0 = __float2bfloat16(x0), h1 = __float2bfloat16(x1);
    float r0 = x0 - __bfloat162float(h0), r1 = x1 - __bfloat162float(h1);
    __nv_bfloat16 l0 = __float2bfloat16(r0), l1 = __float2bfloat16(r1);
    hi = (uint32_t)__bfloat16_as_ushort(h0) | ((uint32_t)__bfloat16_as_ushort(h1) << 16);
    lo = (uint32_t)__bfloat16_as_ushort(l0) | ((uint32_t)__bfloat16_as_ushort(l1) << 16);
}

// ============================================================
// GEMM body: C[M,512] = A[M,512] @ W[512,512] + bias  (split precision)
// block 256 (8 warps: 4 m x 2 n), tile 128x128, warp tile 32x64
// sumA4: A is base of 4 partial planes (stride Mrows*DMc) summed on load.
// ============================================================
__device__ __forceinline__ void gemm_body(
    const float* __restrict__ A, const float* __restrict__ W,
    const float* __restrict__ bias,
    float* __restrict__ C, uint32_t* __restrict__ Hp, uint32_t* __restrict__ Lp,
    __nv_bfloat16* __restrict__ Ht, __nv_bfloat16* __restrict__ Lt,
    bool writeF, bool writeP, bool writeT, bool sumA4, int mb, int nb)
{
    __shared__ uint32_t sm[4 * 128 * 20];
    const int ASH = 0, ASL = 2560, BSH = 5120, BSL = 7680, RS = 20;

    const int tid = threadIdx.x;
    const int w = tid >> 5, lane = tid & 31;
    const int g = lane >> 2, t = lane & 3;
    const int wm = (w >> 1) * 32, wn = (w & 1) * 64;
    const uint32_t sbase = smem_u32(sm);

    float c[2][8][4];
#pragma unroll
    for (int mi = 0; mi < 2; mi++)
#pragma unroll
        for (int nf = 0; nf < 8; nf++)
#pragma unroll
            for (int r = 0; r < 4; r++) c[mi][nf][r] = 0.f;

    const int arow_i = tid >> 1, aseg = tid & 1;
    const float* arow = A + (size_t)(mb + arow_i) * DMc;
    const int bn = tid & 127, bkh = tid >> 7;

    for (int kc = 0; kc < 16; kc++) {
#pragma unroll
        for (int i = 0; i < 4; i++) {
            int f4 = aseg * 4 + i;
            float4 v = *(const float4*)(arow + kc * 32 + f4 * 4);
            if (sumA4) {
#pragma unroll
                for (int s2 = 1; s2 < KS; s2++) {
                    float4 v2 = *(const float4*)(arow + (size_t)s2 * Mrows * DMc + kc * 32 + f4 * 4);
                    v.x += v2.x; v.y += v2.y; v.z += v2.z; v.w += v2.w;
                }
            }
            uint32_t h0, l0, h1, l1;
            split2(v.x, v.y, h0, l0);
            split2(v.z, v.w, h1, l1);
            sm[ASH + arow_i * RS + f4 * 2]     = h0;
            sm[ASH + arow_i * RS + f4 * 2 + 1] = h1;
            sm[ASL + arow_i * RS + f4 * 2]     = l0;
            sm[ASL + arow_i * RS + f4 * 2 + 1] = l1;
        }
#pragma unroll
        for (int i = 0; i < 8; i++) {
            int kp = bkh * 8 + i;
            const float* wp = W + (size_t)(kc * 32 + 2 * kp) * DMc + nb + bn;
            float w0 = wp[0], w1 = wp[DMc];
            uint32_t hi, lo;
            split2(w0, w1, hi, lo);
            sm[BSH + bn * RS + kp] = hi;
            sm[BSL + bn * RS + kp] = lo;
        }
        __syncthreads();

#pragma unroll
        for (int kk = 0; kk < 2; kk++) {
            uint32_t ah[2][4], al[2][4];
#pragma unroll
            for (int mi = 0; mi < 2; mi++) {
                ldsm4(ah[mi], addrA(sbase + ASH * 4, wm + mi * 16, kk * 16, lane, RS));
                ldsm4(al[mi], addrA(sbase + ASL * 4, wm + mi * 16, kk * 16, lane, RS));
            }
#pragma unroll
            for (int nb2 = 0; nb2 < 4; nb2++) {
                uint32_t bhf[4], blf[4];
                ldsm4(bhf, addrB(sbase + BSH * 4, wn + nb2 * 16, kk * 16, lane, RS));
                ldsm4(blf, addrB(sbase + BSL * 4, wn + nb2 * 16, kk * 16, lane, RS));
#pragma unroll
                for (int mi = 0; mi < 2; mi++) {
                    mma16816(c[mi][2 * nb2],     ah[mi], bhf[0], bhf[1]);
                    mma16816(c[mi][2 * nb2],     ah[mi], blf[0], blf[1]);
                    mma16816(c[mi][2 * nb2],     al[mi], bhf[0], bhf[1]);
                    mma16816(c[mi][2 * nb2 + 1], ah[mi], bhf[2], bhf[3]);
                    mma16816(c[mi][2 * nb2 + 1], ah[mi], blf[2], blf[3]);
                    mma16816(c[mi][2 * nb2 + 1], al[mi], bhf[2], bhf[3]);
                }
            }
        }
        __syncthreads();
    }

#pragma unroll
    for (int mi = 0; mi < 2; mi++)
#pragma unroll
        for (int hh = 0; hh < 2; hh++) {
            int row = mb + wm + mi * 16 + hh * 8 + g;
#pragma unroll
            for (int nf = 0; nf < 8; nf++) {
                int col = nb + wn + nf * 8 + 2 * t;
                float2 bv = *(const float2*)(bias + col);
                float ox = c[mi][nf][hh * 2 + 0] + bv.x;
                float oy = c[mi][nf][hh * 2 + 1] + bv.y;
                if (writeF)
                    *(float2*)(C + (size_t)row * DMc + col) = make_float2(ox, oy);
                if (writeP) {
                    uint32_t hi, lo;
                    split2(ox, oy, hi, lo);
                    size_t pi = ((size_t)row * DMc + col) >> 1;
                    Hp[pi] = hi;
                    Lp[pi] = lo;
                }
                if (writeT) {
                    __nv_bfloat16 h0 = __float2bfloat16(ox);
                    __nv_bfloat16 l0 = __float2bfloat16(ox - __bfloat162float(h0));
                    __nv_bfloat16 h1 = __float2bfloat16(oy);
                    __nv_bfloat16 l1 = __float2bfloat16(oy - __bfloat162float(h1));
                    size_t i0 = ((size_t)(((row >> 11) * Hc + (col >> 6)) * DHc + (col & 63))) * Sc
                              + (row & (Sc - 1));
                    Ht[i0] = h0; Lt[i0] = l0;
                    Ht[i0 + Sc] = h1; Lt[i0 + Sc] = l1;
                }
            }
        }
}

// K1: fused Q/K/V projections. grid = (4, 32, 3), block 256.
__global__ __launch_bounds__(256, 1)
void qkv_kernel(const float* __restrict__ q, const float* __restrict__ k,
                const float* __restrict__ v,
                const float* __restrict__ Wq, const float* __restrict__ Wk,
                const float* __restrict__ Wv,
                const float* __restrict__ bq, const float* __restrict__ bk,
                const float* __restrict__ bv)
{
    const int mb = blockIdx.y * 128, nb = blockIdx.x * 128;
    if (blockIdx.z == 0)
        gemm_body(q, Wq, bq, g_qp, g_qph, g_qpl, nullptr, nullptr, true, true, false, false, mb, nb);
    else if (blockIdx.z == 1)
        gemm_body(k, Wk, bk, nullptr, g_kph, g_kpl, nullptr, nullptr, false, true, false, false, mb, nb);
    else
        gemm_body(v, Wv, bv, nullptr, nullptr, nullptr, g_vth, g_vtl, false, false, true, false, mb, nb);
}

// K5: final projection (sums 4 attnv partial planes on A load). grid = (4, 32).
__global__ __launch_bounds__(256, 1)
void out_kernel(const float* __restrict__ Wo, const float* __restrict__ bo,
                float* __restrict__ out)
{
    gemm_body(g_opart, Wo, bo, out, nullptr, nullptr, nullptr, nullptr,
              true, false, false, true, blockIdx.y * 128, blockIdx.x * 128);
}

// ============================================================
// K2: a,b heads. grid = 128, block 256, warp handles 4 rows, W cached in smem.
// ============================================================
__global__ __launch_bounds__(256)
void ab_kernel(const float* __restrict__ Wa, const float* __restrict__ ba,
               const float* __restrict__ Wb, const float* __restrict__ bb)
{
    __shared__ float4 sWa[512][2];
    __shared__ float4 sWb[512][2];
    const int tid = threadIdx.x;
#pragma unroll
    for (int i = 0; i < 4; i++) {
        int idx = tid + i * 256;
        ((float4*)sWa)[idx] = ((const float4*)Wa)[idx];
        ((float4*)sWb)[idx] = ((const float4*)Wb)[idx];
    }
    __syncthreads();

    const int w = tid >> 5, lane = tid & 31;
    const int rbase = blockIdx.x * 32 + w * 4;

    float acc[4][16];
#pragma unroll
    for (int j = 0; j < 4; j++)
#pragma unroll
        for (int h = 0; h < 16; h++) acc[j][h] = 0.f;

#pragma unroll
    for (int tt = 0; tt < 4; tt++) {
        const int d0 = tt * 128 + lane * 4;
        float4 x[4];
#pragma unroll
        for (int j = 0; j < 4; j++)
            x[j] = *(const float4*)(g_qp + (size_t)(rbase + j) * DMc + d0);
#pragma unroll
        for (int dd = 0; dd < 4; dd++) {
            float4 wa0 = sWa[d0 + dd][0], wa1 = sWa[d0 + dd][1];
            float4 wb0 = sWb[d0 + dd][0], wb1 = sWb[d0 + dd][1];
#pragma unroll
            for (int j = 0; j < 4; j++) {
                float xv = (&x[j].x)[dd];
                acc[j][0]  = fmaf(xv, wa0.x, acc[j][0]);
                acc[j][1]  = fmaf(xv, wa0.y, acc[j][1]);
                acc[j][2]  = fmaf(xv, wa0.z, acc[j][2]);
                acc[j][3]  = fmaf(xv, wa0.w, acc[j][3]);
                acc[j][4]  = fmaf(xv, wa1.x, acc[j][4]);
                acc[j][5]  = fmaf(xv, wa1.y, acc[j][5]);
                acc[j][6]  = fmaf(xv, wa1.z, acc[j][6]);
                acc[j][7]  = fmaf(xv, wa1.w, acc[j][7]);
                acc[j][8]  = fmaf(xv, wb0.x, acc[j][8]);
                acc[j][9]  = fmaf(xv, wb0.y, acc[j][9]);
                acc[j][10] = fmaf(xv, wb0.z, acc[j][10]);
                acc[j][11] = fmaf(xv, wb0.w, acc[j][11]);
                acc[j][12] = fmaf(xv, wb1.x, acc[j][12]);
                acc[j][13] = fmaf(xv, wb1.y, acc[j][13]);
                acc[j][14] = fmaf(xv, wb1.z, acc[j][14]);
                acc[j][15] = fmaf(xv, wb1.w, acc[j][15]);
            }
        }
    }
#pragma unroll
    for (int o = 16; o > 0; o >>= 1)
#pragma unroll
        for (int j = 0; j < 4; j++)
#pragma unroll
            for (int h = 0; h < 16; h++)
                acc[j][h] += __shfl_xor_sync(0xffffffff, acc[j][h], o);

    if (lane < 4) {
        int row = rbase + lane;
        int b = row >> 11, s = row & (Sc - 1);
#pragma unroll
        for (int h = 0; h < 8; h++) {
            g_a[(b * Hc + h) * Sc + s] = acc[lane][h] + ba[h];
            g_b[(b * Hc + h) * Sc + s] = acc[lane][h + 8] + bb[h];
        }
    }
}

// Shared smem layout for stats kernel (dynamic, 73728 B)
static constexpr int QH_O = 0, QL_O = 4608, KVH_O = 9216, KVL_O = 13824;
static constexpr int RSQ = 36;
static constexpr int DYN_SMEM = 18432 * 4;

// copy 128 rows x 64 bf16 (32 u32) from packed global hi/lo into smem stride-36 rows
__device__ __forceinline__ void stage_copy(uint32_t* sm, int offH, int offL,
        const uint32_t* __restrict__ srcH, const uint32_t* __restrict__ srcL,
        size_t rowbase, int tid)
{
    const int row = tid >> 1, half = tid & 1;
    const size_t s0 = rowbase + (size_t)row * (DMc / 2) + half * 16;
    const uint4* sH = (const uint4*)(srcH + s0);
    const uint4* sL = (const uint4*)(srcL + s0);
    uint4* dH = (uint4*)(sm + offH + row * RSQ + half * 16);
    uint4* dL = (uint4*)(sm + offL + row * RSQ + half * 16);
#pragma unroll
    for (int i = 0; i < 4; i++) { dH[i] = sH[i]; dL[i] = sL[i]; }
}

__device__ __forceinline__ void score_mma(float (&c)[2][8][4], uint32_t sbase,
                                          int wm, int wn, int lane)
{
#pragma unroll
    for (int mi = 0; mi < 2; mi++)
#pragma unroll
        for (int nf = 0; nf < 8; nf++)
#pragma unroll
            for (int r = 0; r < 4; r++) c[mi][nf][r] = 0.f;
#pragma unroll
    for (int kk = 0; kk < 4; kk++) {
        uint32_t ah[2][4], al[2][4];
#pragma unroll
        for (int mi = 0; mi < 2; mi++) {
            ldsm4(ah[mi], addrA(sbase + QH_O * 4, wm + mi * 16, kk * 16, lane, RSQ));
            ldsm4(al[mi], addrA(sbase + QL_O * 4, wm + mi * 16, kk * 16, lane, RSQ));
        }
#pragma unroll
        for (int nb2 = 0; nb2 < 4; nb2++) {
            uint32_t bhf[4], blf[4];
            ldsm4(bhf, addrB(sbase + KVH_O * 4, wn + nb2 * 16, kk * 16, lane, RSQ));
            ldsm4(blf, addrB(sbase + KVL_O * 4, wn + nb2 * 16, kk * 16, lane, RSQ));
#pragma unroll
            for (int mi = 0; mi < 2; mi++) {
                mma16816(c[mi][2 * nb2],     ah[mi], bhf[0], bhf[1]);
                mma16816(c[mi][2 * nb2],     ah[mi], blf[0], blf[1]);
                mma16816(c[mi][2 * nb2],     al[mi], bhf[0], bhf[1]);
                mma16816(c[mi][2 * nb2 + 1], ah[mi], bhf[2], bhf[3]);
                mma16816(c[mi][2 * nb2 + 1], ah[mi], blf[2], blf[3]);
                mma16816(c[mi][2 * nb2 + 1], al[mi], bhf[2], bhf[3]);
            }
        }
    }
}

// ============================================================
// K3: stats partial — 512-key slice per block; writes raw logits + partial (m,s).
// grid = (16 qtile, 16 bh, 4 ks), block = 256.
// ============================================================
__global__ __launch_bounds__(256, 1)
void stats_part_kernel(const float* __restrict__ xdiff, const int* __restrict__ mask,
                       float* __restrict__ attn)
{
    extern __shared__ uint32_t sm[];
    const int tid = threadIdx.x, w = tid >> 5, lane = tid & 31;
    const int g = lane >> 2, t = lane & 3;
    const int bh = blockIdx.y, b = bh >> 3, h = bh & 7;
    const int qb = blockIdx.x * 128;
    const int ks = blockIdx.z;
    const int wm = (w >> 1) * 32, wn = (w & 1) * 64;
    const uint32_t sbase = smem_u32(sm);

    stage_copy(sm, QH_O, QL_O, g_qph, g_qpl,
               (size_t)(b * Sc + qb) * (DMc / 2) + h * (DHc / 2), tid);
    __syncthreads();

    float rm[4], rs[4], aqv[4], bqv[4];
    const float* xr[4];
    float* lrow[4];
#pragma unroll
    for (int mi = 0; mi < 2; mi++)
#pragma unroll
        for (int hh = 0; hh < 2; hh++) {
            int idx = mi * 2 + hh;
            int q = qb + wm + mi * 16 + hh * 8 + g;
            rm[idx] = -3.0e38f; rs[idx] = 0.f;
            aqv[idx] = g_a[bh * Sc + q];
            bqv[idx] = g_b[bh * Sc + q];
            xr[idx] = xdiff + ((size_t)b * Sc + q) * Sc;
            lrow[idx] = attn + ((size_t)bh * Sc + q) * Sc;
        }
    const int* mrow = mask + b * Sc;

    for (int kt = ks * 4; kt < ks * 4 + 4; kt++) {
        const int kb = kt * 128;
        stage_copy(sm, KVH_O, KVL_O, g_kph, g_kpl,
                   (size_t)(b * Sc + kb) * (DMc / 2) + h * (DHc / 2), tid);
        __syncthreads();

        float c[2][8][4];
        score_mma(c, sbase, wm, wn, lane);
        __syncthreads();

#pragma unroll
        for (int mi = 0; mi < 2; mi++)
#pragma unroll
            for (int nf = 0; nf < 8; nf++) {
                int col = kb + wn + nf * 8 + 2 * t;
                int2 mv = *(const int2*)(mrow + col);
                float mt0 = (float)mv.x * -1e9f, mt1 = (float)mv.y * -1e9f;
#pragma unroll
                for (int hh = 0; hh < 2; hh++) {
                    int idx = mi * 2 + hh;
                    float2 xd = *(const float2*)(xr[idx] + col);
                    float l0 = c[mi][nf][hh * 2 + 0] * 0.125f + mt0 + aqv[idx] * xd.x + bqv[idx] * xd.x * xd.x;
                    float l1 = c[mi][nf][hh * 2 + 1] * 0.125f + mt1 + aqv[idx] * xd.y + bqv[idx] * xd.y * xd.y;
                    *(float2*)(lrow[idx] + col) = make_float2(l0, l1);
                    float mx = fmaxf(l0, l1);
                    if (mx > rm[idx]) { rs[idx] *= __expf(rm[idx] - mx); rm[idx] = mx; }
                    rs[idx] += __expf(l0 - rm[idx]) + __expf(l1 - rm[idx]);
                }
            }
    }

    // quad reduce
#pragma unroll
    for (int off = 1; off <= 2; off <<= 1)
#pragma unroll
        for (int i = 0; i < 4; i++) {
            float om = __shfl_xor_sync(0xffffffff, rm[i], off);
            float os = __shfl_xor_sync(0xffffffff, rs[i], off);
            float nm = fmaxf(rm[i], om);
            rs[i] = rs[i] * __expf(rm[i] - nm) + os * __expf(om - nm);
            rm[i] = nm;
        }
    __syncthreads();
    float2* red = (float2*)sm;
    if (t == 0) {
#pragma unroll
        for (int i = 0; i < 4; i++) {
            int rl = (i >> 1) * 16 + (i & 1) * 8 + g;
            red[w * 32 + rl] = make_float2(rm[i], rs[i]);
        }
    }
    __syncthreads();
    if (!(w & 1) && t == 0) {
#pragma unroll
        for (int i = 0; i < 4; i++) {
            int rl = (i >> 1) * 16 + (i & 1) * 8 + g;
            float2 p = red[(w ^ 1) * 32 + rl];
            float nm = fmaxf(rm[i], p.x);
            float ns = rs[i] * __expf(rm[i] - nm) + p.y * __expf(p.x - nm);
            int q = qb + wm + rl;
            g_pstat[(ks * BHc + bh) * Sc + q] = make_float2(nm, ns);
        }
    }
}

// K3b: merge 4 partial (m,s) -> final rmax/rinv. grid = 128, block = 256.
__global__ __launch_bounds__(256)
void stat_merge_kernel()
{
    const int idx = blockIdx.x * 256 + threadIdx.x;   // 0..32767
    float m = -3.0e38f, s = 0.f;
#pragma unroll
    for (int ks = 0; ks < KS; ks++) {
        float2 p = g_pstat[ks * BHc * Sc + idx];
        float nm = fmaxf(m, p.x);
        s = s * __expf(m - nm) + p.y * __expf(p.x - nm);
        m = nm;
    }
    g_rmax[idx] = m;
    g_rinv[idx] = 1.0f / s;
}

// ============================================================
// K4: attnV partial — 512-key slice; read raw logits, normalize, write attn, P@V.
// grid = (32 qtile64, 16 bh, 4 ks), block = 256 (8 warps: 4 m16 x 2 k-half).
// ============================================================
static constexpr int RSV = 68;
__global__ __launch_bounds__(256)
void attnv_tc_kernel(float* __restrict__ attn)
{
    __shared__ uint32_t sm[8704];                 // VH 4352 + VL 4352 words
    const int VH_O = 0, VL_O = 4352;
    const int tid = threadIdx.x, w = tid >> 5, lane = tid & 31;
    const int g = lane >> 2, t = lane & 3;
    const int bh = blockIdx.y;
    const int qb = blockIdx.x * 64;
    const int ks = blockIdx.z;
    const int wm = (w >> 1) * 16, wn = (w & 1) * 64;
    const uint32_t sbase = smem_u32(sm);

    float msv[2], invv[2];
    float* arow[2];
#pragma unroll
    for (int hh = 0; hh < 2; hh++) {
        int q = qb + wm + hh * 8 + g;
        msv[hh] = g_rmax[bh * Sc + q];
        invv[hh] = g_rinv[bh * Sc + q];
        arow[hh] = attn + ((size_t)bh * Sc + q) * Sc;
    }

    float o[8][4];
#pragma unroll
    for (int nf = 0; nf < 8; nf++)
#pragma unroll
        for (int r = 0; r < 4; r++) o[nf][r] = 0.f;

    const int vrow = tid >> 2, vseg = tid & 3;    // 64 d-rows, 4 segs

    for (int kt = ks * 4; kt < ks * 4 + 4; kt++) {
        const int kb = kt * 128;
        // stage V^T tile (64 d x 128 k) hi/lo from preconverted transposed arrays
        {
            const uint4* sH = (const uint4*)g_vth + ((size_t)(bh * DHc + vrow) * Sc + kb) / 8;
            const uint4* sL = (const uint4*)g_vtl + ((size_t)(bh * DHc + vrow) * Sc + kb) / 8;
            uint4* dH = (uint4*)(sm + VH_O + vrow * RSV);
            uint4* dL = (uint4*)(sm + VL_O + vrow * RSV);
#pragma unroll
            for (int i = 0; i < 4; i++) {
                dH[vseg * 4 + i] = sH[vseg * 4 + i];
                dL[vseg * 4 + i] = sL[vseg * 4 + i];
            }
        }
        __syncthreads();

#pragma unroll
        for (int j = 0; j < 4; j++) {
            uint32_t pah[4], pal[4];
#pragma unroll
            for (int nn = 0; nn < 2; nn++) {
                int col = kb + wn + (2 * j + nn) * 8 + 2 * t;
#pragma unroll
                for (int hh = 0; hh < 2; hh++) {
                    float2 L = *(const float2*)(arow[hh] + col);
                    float p0 = __expf(L.x - msv[hh]) * invv[hh];
                    float p1 = __expf(L.y - msv[hh]) * invv[hh];
                    *(float2*)(arow[hh] + col) = make_float2(p0, p1);
                    split2(p0, p1, pah[nn * 2 + hh], pal[nn * 2 + hh]);
                }
            }
#pragma unroll
            for (int nd = 0; nd < 4; nd++) {
                uint32_t vh[4], vl[4];
                ldsm4(vh, addrB(sbase + VH_O * 4, nd * 16, wn + j * 16, lane, RSV));
                ldsm4(vl, addrB(sbase + VL_O * 4, nd * 16, wn + j * 16, lane, RSV));
                mma16816(o[2 * nd],     pah, vh[0], vh[1]);
                mma16816(o[2 * nd],     pah, vl[0], vl[1]);
                mma16816(o[2 * nd],     pal, vh[0], vh[1]);
                mma16816(o[2 * nd + 1], pah, vh[2], vh[3]);
                mma16816(o[2 * nd + 1], pah, vl[2], vl[3]);
                mma16816(o[2 * nd + 1], pal, vh[2], vh[3]);
            }
        }
        __syncthreads();
    }

    // reduce across warp pairs (two k-halves); stride 33 floats per lane slot
    float* red = (float*)sm;
    if (w & 1) {
        float* dst = red + ((w >> 1) * 32 + lane) * 33;
#pragma unroll
        for (int nf = 0; nf < 8; nf++)
#pragma unroll
            for (int r = 0; r < 4; r++)
                dst[nf * 4 + r] = o[nf][r];
    }
    __syncthreads();
    if (!(w & 1)) {
        const int b = bh >> 3, h = bh & 7;
        const float* src = red + ((w >> 1) * 32 + lane) * 33;
#pragma unroll
        for (int nf = 0; nf < 8; nf++)
#pragma unroll
            for (int r = 0; r < 4; r++)
                o[nf][r] += src[nf * 4 + r];
        float* obase = g_opart + (size_t)ks * Mrows * DMc;
#pragma unroll
        for (int hh = 0; hh < 2; hh++) {
            int q = qb + wm + hh * 8 + g;
#pragma unroll
            for (int nf = 0; nf < 8; nf++) {
                float2 val = make_float2(o[nf][hh * 2 + 0], o[nf][hh * 2 + 1]);
                *(float2*)(obase + (size_t)(b * Sc + q) * DMc + h * DHc + nf * 8 + 2 * t) = val;
            }
        }
    }
}

// ============================================================
extern "C" void kernel_launch(void* const* d_in, const int* in_sizes, int n_in,
                              void* d_out, int out_size)
{
    const float* q     = (const float*)d_in[0];
    const float* k     = (const float*)d_in[1];
    const float* v     = (const float*)d_in[2];
    const float* xdiff = (const float*)d_in[3];
    const int*   mask  = (const int*)d_in[4];
    const float* Wq = (const float*)d_in[5];
    const float* bq = (const float*)d_in[6];
    const float* Wk = (const float*)d_in[7];
    const float* bk = (const float*)d_in[8];
    const float* Wv = (const float*)d_in[9];
    const float* bv = (const float*)d_in[10];
    const float* Wa = (const float*)d_in[11];
    const float* ba = (const float*)d_in[12];
    const float* Wb = (const float*)d_in[13];
    const float* bb = (const float*)d_in[14];
    const float* Wo = (const float*)d_in[15];
    const float* bo = (const float*)d_in[16];

    float* out  = (float*)d_out;                 // (B,S,DM)
    float* attn = out + (size_t)Bc * Sc * DMc;   // (B,H,S,S)

    cudaFuncSetAttribute(stats_part_kernel, cudaFuncAttributeMaxDynamicSharedMemorySize, DYN_SMEM);

    qkv_kernel<<<dim3(DMc / 128, Mrows / 128, 3), 256>>>(q, k, v, Wq, Wk, Wv, bq, bk, bv);
    ab_kernel<<<Mrows / 32, 256>>>(Wa, ba, Wb, bb);
    stats_part_kernel<<<dim3(Sc / 128, BHc, KS), 256, DYN_SMEM>>>(xdiff, mask, attn);
    stat_merge_kernel<<<BHc * Sc / 256, 256>>>();
    attnv_tc_kernel<<<dim3(Sc / 64, BHc, KS), 256>>>(attn);
    out_kernel<<<dim3(DMc / 128, Mrows / 128), 256>>>(Wo, bo, out);
}